// round 2
// baseline (speedup 1.0000x reference)
#include <cuda_runtime.h>
#include <cstdint>

#define BATCH 8
#define NNODES 50000
#define DIM 64
#define ROW_F4 16                 // float4 per 64-float row
#define TOTAL_ROWS ((size_t)BATCH * NNODES)   // 400000

// Scratch for agg (B, N, 64) fp32 = 102.4 MB.
// Declared as float4 so the base is 16-byte aligned (float[] is only 4B-aligned
// -> wide LDG/STG/red.v4 would trap err715).
__device__ float4 g_agg[TOTAL_ROWS * ROW_F4];

// Flag: 1 if edge_index words are int64 (odd 32-bit words all zero), else 0.
__device__ int g_is64;

// ---------------------------------------------------------------------------
// Kernel 0: detect edge_index dtype. int64 little-endian => every odd 32-bit
// word is a (zero) high half. int32 => odd words are dst indices (non-zero
// with overwhelming probability over 16k samples).
// ---------------------------------------------------------------------------
__global__ void detect_dtype_kernel(const int* __restrict__ w, int nwords) {
    __shared__ int any_nonzero;
    if (threadIdx.x == 0) any_nonzero = 0;
    __syncthreads();
    int limit = nwords / 2;
    if (limit > 16384) limit = 16384;
    for (int i = threadIdx.x; i < limit; i += blockDim.x) {
        if (w[2 * i + 1] != 0) any_nonzero = 1;
    }
    __syncthreads();
    if (threadIdx.x == 0) g_is64 = (any_nonzero == 0) ? 1 : 0;
}

// ---------------------------------------------------------------------------
// Kernel 1: zero the agg buffer (float4 grid-stride)
// ---------------------------------------------------------------------------
__global__ void zero_agg_kernel() {
    const size_t total4 = TOTAL_ROWS * ROW_F4;   // 6.4M float4
    float4 z = make_float4(0.f, 0.f, 0.f, 0.f);
    for (size_t i = (size_t)blockIdx.x * blockDim.x + threadIdx.x;
         i < total4;
         i += (size_t)gridDim.x * blockDim.x) {
        g_agg[i] = z;
    }
}

// ---------------------------------------------------------------------------
// Kernel 2: edge scatter. One warp per edge; handles all 8 batches.
// Per warp: 128 float4 (8 batches x 16 float4/row) -> 4 per lane.
// Loads first (MLP=4), then fire-and-forget vector reductions.
// ---------------------------------------------------------------------------
__global__ void scatter_kernel(const float* __restrict__ x,
                               const void* __restrict__ edges_raw,
                               int nwords) {
    int is64 = g_is64;
    // Actual edge count: nwords may be int32-word count or "element" count.
    int num_edges;
    if (is64) {
        num_edges = (nwords >= 3000000) ? (nwords >> 2) : (nwords >> 1);
    } else {
        num_edges = nwords >> 1;
    }

    int warp_id = (int)((blockIdx.x * (size_t)blockDim.x + threadIdx.x) >> 5);
    int lane = threadIdx.x & 31;
    if (warp_id >= num_edges) return;

    long long src, dst;
    if (is64) {
        const long long* e = (const long long*)edges_raw;
        src = e[2 * (long long)warp_id + 0];
        dst = e[2 * (long long)warp_id + 1];
    } else {
        const int* e = (const int*)edges_raw;
        src = e[2 * warp_id + 0];
        dst = e[2 * warp_id + 1];
    }

    const float4* xs = reinterpret_cast<const float4*>(x);

    float4 v[4];
#pragma unroll
    for (int i = 0; i < 4; i++) {
        int idx = i * 32 + lane;          // 0..127
        int b = idx >> 4;                 // batch
        int c = idx & 15;                 // float4 within row
        v[i] = xs[((size_t)b * NNODES + (size_t)src) * ROW_F4 + c];
    }
#pragma unroll
    for (int i = 0; i < 4; i++) {
        int idx = i * 32 + lane;
        int b = idx >> 4;
        int c = idx & 15;
        float4* p = &g_agg[((size_t)b * NNODES + (size_t)dst) * ROW_F4 + c];
        asm volatile("red.global.add.v4.f32 [%0], {%1, %2, %3, %4};"
                     :: "l"(p), "f"(v[i].x), "f"(v[i].y), "f"(v[i].z), "f"(v[i].w)
                     : "memory");
    }
}

// ---------------------------------------------------------------------------
// Kernel 3: fused dual-GEMM + bias + ReLU.
//   out[row, o] = relu( sum_k x[row,k]*Ws[o,k] + agg[row,k]*Wn[o,k] + bs[o]+bn[o] )
// Block = 128 threads (4 warps). Warp w owns outputs [16w, 16w+16).
// Lane = row within a 32-row group; block processes 256 rows (8 groups).
// Weights in smem transposed [k][o]; weight LDS.128 are warp-uniform
// (same address across lanes -> broadcast, conflict-free).
// ---------------------------------------------------------------------------
__global__ __launch_bounds__(128) void gemm_relu_kernel(
        const float* __restrict__ x,
        const float* __restrict__ Ws, const float* __restrict__ bs,
        const float* __restrict__ Wn, const float* __restrict__ bn,
        float* __restrict__ out) {
    __shared__ float sWs[DIM * DIM];   // [k][o]
    __shared__ float sWn[DIM * DIM];   // [k][o]
    __shared__ float sb[DIM];

    int tid = threadIdx.x;
    for (int i = tid; i < DIM * DIM; i += 128) {
        int o = i >> 6;
        int k = i & 63;
        sWs[k * DIM + o] = Ws[i];
        sWn[k * DIM + o] = Wn[i];
    }
    if (tid < DIM) sb[tid] = bs[tid] + bn[tid];
    __syncthreads();

    int warp = tid >> 5;
    int lane = tid & 31;
    int o0 = warp * 16;

    size_t base_row = (size_t)blockIdx.x * 256;

#pragma unroll 1
    for (int it = 0; it < 8; it++) {
        size_t row = base_row + (size_t)it * 32 + lane;
        if (row >= TOTAL_ROWS) break;

        float acc[16];
#pragma unroll
        for (int i = 0; i < 16; i++) acc[i] = sb[o0 + i];

        const float4* xr = reinterpret_cast<const float4*>(x + row * DIM);
        const float4* ar = &g_agg[row * ROW_F4];

#pragma unroll
        for (int k4 = 0; k4 < 16; k4++) {
            float4 xv = xr[k4];
            float4 av = ar[k4];
            float xk[4] = {xv.x, xv.y, xv.z, xv.w};
            float ak[4] = {av.x, av.y, av.z, av.w};
#pragma unroll
            for (int j = 0; j < 4; j++) {
                int k = k4 * 4 + j;
                const float4* wsp = reinterpret_cast<const float4*>(&sWs[k * DIM + o0]);
                const float4* wnp = reinterpret_cast<const float4*>(&sWn[k * DIM + o0]);
#pragma unroll
                for (int q = 0; q < 4; q++) {
                    float4 ws = wsp[q];
                    float4 wn = wnp[q];
                    acc[q * 4 + 0] += xk[j] * ws.x + ak[j] * wn.x;
                    acc[q * 4 + 1] += xk[j] * ws.y + ak[j] * wn.y;
                    acc[q * 4 + 2] += xk[j] * ws.z + ak[j] * wn.z;
                    acc[q * 4 + 3] += xk[j] * ws.w + ak[j] * wn.w;
                }
            }
        }

        float4* orow = reinterpret_cast<float4*>(out + row * DIM + o0);
#pragma unroll
        for (int q = 0; q < 4; q++) {
            float4 r;
            r.x = fmaxf(acc[q * 4 + 0], 0.f);
            r.y = fmaxf(acc[q * 4 + 1], 0.f);
            r.z = fmaxf(acc[q * 4 + 2], 0.f);
            r.w = fmaxf(acc[q * 4 + 3], 0.f);
            orow[q] = r;
        }
    }
}

// ---------------------------------------------------------------------------
// Launch. Inputs per metadata order:
//   d_in[0] x          (B,N,64) f32
//   d_in[1] edge_index (E,2)    int64 or int32 (runtime-detected)
//   d_in[2] W_self     (64,64)  f32
//   d_in[3] b_self     (64,)    f32
//   d_in[4] W_neigh    (64,64)  f32
//   d_in[5] b_neigh    (64,)    f32
// ---------------------------------------------------------------------------
extern "C" void kernel_launch(void* const* d_in, const int* in_sizes, int n_in,
                              void* d_out, int out_size) {
    const float* x = (const float*)d_in[0];
    const void* edges = d_in[1];
    const float* Ws = (const float*)d_in[2];
    const float* bs = (const float*)d_in[3];
    const float* Wn = (const float*)d_in[4];
    const float* bn = (const float*)d_in[5];
    float* out = (float*)d_out;

    int nwords = in_sizes[1];           // count in (at least) 32-bit words/elements
    int max_edges = nwords / 2;         // upper bound on edge count

    // 0) detect edge dtype
    detect_dtype_kernel<<<1, 256>>>((const int*)edges, nwords);

    // 1) zero agg
    zero_agg_kernel<<<2048, 256>>>();

    // 2) scatter: one warp per edge, 8 warps per block (grid sized for the
    //    max possible edge count; excess warps exit after reading the flag)
    int warps_per_block = 8;
    int blocks = (max_edges + warps_per_block - 1) / warps_per_block;
    scatter_kernel<<<blocks, warps_per_block * 32>>>(x, edges, nwords);

    // 3) fused dual-GEMM + bias + relu: 256 rows per block
    int gblocks = (int)((TOTAL_ROWS + 255) / 256);
    gemm_relu_kernel<<<gblocks, 128>>>(x, Ws, bs, Wn, bn, out);
}

// round 3
// speedup vs baseline: 1.2844x; 1.2844x over previous
#include <cuda_runtime.h>
#include <cstdint>

#define BATCH 8
#define NNODES 50000
#define DIM 64
#define ROW_F4 16                 // float4 per 64-float row
#define TOTAL_ROWS ((size_t)BATCH * NNODES)   // 400000

// Scratch for agg (B, N, 64) fp32 = 102.4 MB. float4 => 16B-aligned base.
__device__ float4 g_agg[TOTAL_ROWS * ROW_F4];

// Flag: 1 if edge_index words are int64 (odd 32-bit words all zero), else 0.
__device__ int g_is64;

// ---------------------------------------------------------------------------
// packed f32x2 helpers (sm_103a packed fp32 pipe; 2x FFMA throughput)
// ---------------------------------------------------------------------------
__device__ __forceinline__ unsigned long long pack2(float a, float b) {
    unsigned long long r;
    asm("mov.b64 %0, {%1, %2};" : "=l"(r) : "f"(a), "f"(b));
    return r;
}
__device__ __forceinline__ unsigned long long fma2(unsigned long long a,
                                                   unsigned long long b,
                                                   unsigned long long c) {
    unsigned long long d;
    asm("fma.rn.f32x2 %0, %1, %2, %3;" : "=l"(d) : "l"(a), "l"(b), "l"(c));
    return d;
}
__device__ __forceinline__ void unpack2(unsigned long long v, float& lo, float& hi) {
    asm("mov.b64 {%0, %1}, %2;" : "=f"(lo), "=f"(hi) : "l"(v));
}

// ---------------------------------------------------------------------------
// Kernel 0: detect edge_index dtype (int64 LE => odd 32-bit words all zero).
// ---------------------------------------------------------------------------
__global__ void detect_dtype_kernel(const int* __restrict__ w, int nwords) {
    __shared__ int any_nonzero;
    if (threadIdx.x == 0) any_nonzero = 0;
    __syncthreads();
    int limit = nwords / 2;
    if (limit > 16384) limit = 16384;
    for (int i = threadIdx.x; i < limit; i += blockDim.x) {
        if (w[2 * i + 1] != 0) any_nonzero = 1;
    }
    __syncthreads();
    if (threadIdx.x == 0) g_is64 = (any_nonzero == 0) ? 1 : 0;
}

// ---------------------------------------------------------------------------
// Kernel 1: zero the agg buffer
// ---------------------------------------------------------------------------
__global__ void zero_agg_kernel() {
    const size_t total4 = TOTAL_ROWS * ROW_F4;
    float4 z = make_float4(0.f, 0.f, 0.f, 0.f);
    for (size_t i = (size_t)blockIdx.x * blockDim.x + threadIdx.x;
         i < total4;
         i += (size_t)gridDim.x * blockDim.x) {
        g_agg[i] = z;
    }
}

// ---------------------------------------------------------------------------
// Kernel 2: batch-phased edge scatter.
// blockIdx.y = batch; blocks launch x-fastest so concurrent CTAs work on one
// batch => x slice (12.8MB) + agg slice (12.8MB) + edges stay L2-resident.
// One thread per (edge, float4): 16 threads per edge.
// ---------------------------------------------------------------------------
__global__ void scatter_kernel(const float* __restrict__ x,
                               const void* __restrict__ edges_raw,
                               int nwords) {
    int is64 = g_is64;
    int num_edges;
    if (is64) {
        num_edges = (nwords >= 3000000) ? (nwords >> 2) : (nwords >> 1);
    } else {
        num_edges = nwords >> 1;
    }

    size_t gtid = (size_t)blockIdx.x * blockDim.x + threadIdx.x;
    int eid = (int)(gtid >> 4);
    int c = (int)(gtid & 15);
    if (eid >= num_edges) return;

    int b = blockIdx.y;

    long long src, dst;
    if (is64) {
        const long long* e = (const long long*)edges_raw;
        src = e[2 * (long long)eid + 0];
        dst = e[2 * (long long)eid + 1];
    } else {
        const int* e = (const int*)edges_raw;
        src = e[2 * eid + 0];
        dst = e[2 * eid + 1];
    }

    const float4* xs = reinterpret_cast<const float4*>(x);
    float4 v = xs[((size_t)b * NNODES + (size_t)src) * ROW_F4 + c];
    float4* p = &g_agg[((size_t)b * NNODES + (size_t)dst) * ROW_F4 + c];
    asm volatile("red.global.add.v4.f32 [%0], {%1, %2, %3, %4};"
                 :: "l"(p), "f"(v.x), "f"(v.y), "f"(v.z), "f"(v.w)
                 : "memory");
}

// ---------------------------------------------------------------------------
// Kernel 3: fused dual-GEMM + bias + ReLU, packed f32x2 FMA, 2-row blocking.
//   out[row,o] = relu( sum_k x[row,k]*Ws[o,k] + agg[row,k]*Wn[o,k] + b[o] )
// Block = 128 threads (4 warps). Warp w owns outputs [16w, 16w+16) as 8
// f32x2 pairs. Each lane processes rows (base+it*64+lane) and (+32): weight
// LDS amortized over 2 rows. Weight smem transposed [k][o]; warp-uniform
// LDS.128 -> broadcast, conflict-free.
// ---------------------------------------------------------------------------
__global__ __launch_bounds__(128) void gemm_relu_kernel(
        const float* __restrict__ x,
        const float* __restrict__ Ws, const float* __restrict__ bs,
        const float* __restrict__ Wn, const float* __restrict__ bn,
        float* __restrict__ out) {
    __shared__ float sWs[DIM * DIM];   // [k][o]
    __shared__ float sWn[DIM * DIM];   // [k][o]
    __shared__ float sb[DIM];

    int tid = threadIdx.x;
    for (int i = tid; i < DIM * DIM; i += 128) {
        int o = i >> 6;
        int k = i & 63;
        sWs[k * DIM + o] = Ws[i];
        sWn[k * DIM + o] = Wn[i];
    }
    if (tid < DIM) sb[tid] = bs[tid] + bn[tid];
    __syncthreads();

    int warp = tid >> 5;
    int lane = tid & 31;
    int o0 = warp * 16;

    size_t base_row = (size_t)blockIdx.x * 256;

#pragma unroll 1
    for (int it = 0; it < 4; it++) {
        size_t row0 = base_row + (size_t)it * 64 + lane;
        size_t row1 = row0 + 32;
        bool v0 = row0 < TOTAL_ROWS;
        bool v1 = row1 < TOTAL_ROWS;
        if (!v0) break;
        size_t r0 = row0;
        size_t r1 = v1 ? row1 : row0;   // clamp reads; store guarded

        unsigned long long acc0[8], acc1[8];
#pragma unroll
        for (int p = 0; p < 8; p++) {
            unsigned long long b2 = pack2(sb[o0 + 2 * p], sb[o0 + 2 * p + 1]);
            acc0[p] = b2;
            acc1[p] = b2;
        }

        const float4* xr0 = reinterpret_cast<const float4*>(x + r0 * DIM);
        const float4* xr1 = reinterpret_cast<const float4*>(x + r1 * DIM);
        const float4* ar0 = &g_agg[r0 * ROW_F4];
        const float4* ar1 = &g_agg[r1 * ROW_F4];

#pragma unroll
        for (int k4 = 0; k4 < 16; k4++) {
            float4 xv0 = xr0[k4];
            float4 av0 = ar0[k4];
            float4 xv1 = xr1[k4];
            float4 av1 = ar1[k4];
            float x0e[4] = {xv0.x, xv0.y, xv0.z, xv0.w};
            float a0e[4] = {av0.x, av0.y, av0.z, av0.w};
            float x1e[4] = {xv1.x, xv1.y, xv1.z, xv1.w};
            float a1e[4] = {av1.x, av1.y, av1.z, av1.w};
#pragma unroll
            for (int j = 0; j < 4; j++) {
                int k = k4 * 4 + j;
                unsigned long long xs0 = pack2(x0e[j], x0e[j]);
                unsigned long long as0 = pack2(a0e[j], a0e[j]);
                unsigned long long xs1 = pack2(x1e[j], x1e[j]);
                unsigned long long as1 = pack2(a1e[j], a1e[j]);

                const ulonglong2* wsp =
                    reinterpret_cast<const ulonglong2*>(&sWs[k * DIM + o0]);
                const ulonglong2* wnp =
                    reinterpret_cast<const ulonglong2*>(&sWn[k * DIM + o0]);
#pragma unroll
                for (int q = 0; q < 4; q++) {
                    ulonglong2 ws = wsp[q];   // outputs o0+4q .. o0+4q+3
                    ulonglong2 wn = wnp[q];
                    acc0[2 * q + 0] = fma2(xs0, ws.x, acc0[2 * q + 0]);
                    acc0[2 * q + 0] = fma2(as0, wn.x, acc0[2 * q + 0]);
                    acc0[2 * q + 1] = fma2(xs0, ws.y, acc0[2 * q + 1]);
                    acc0[2 * q + 1] = fma2(as0, wn.y, acc0[2 * q + 1]);
                    acc1[2 * q + 0] = fma2(xs1, ws.x, acc1[2 * q + 0]);
                    acc1[2 * q + 0] = fma2(as1, wn.x, acc1[2 * q + 0]);
                    acc1[2 * q + 1] = fma2(xs1, ws.y, acc1[2 * q + 1]);
                    acc1[2 * q + 1] = fma2(as1, wn.y, acc1[2 * q + 1]);
                }
            }
        }

        // epilogue: relu + store
        if (v0) {
            float4* orow = reinterpret_cast<float4*>(out + row0 * DIM + o0);
#pragma unroll
            for (int q = 0; q < 4; q++) {
                float l0, h0, l1, h1;
                unpack2(acc0[2 * q + 0], l0, h0);
                unpack2(acc0[2 * q + 1], l1, h1);
                float4 r;
                r.x = fmaxf(l0, 0.f);
                r.y = fmaxf(h0, 0.f);
                r.z = fmaxf(l1, 0.f);
                r.w = fmaxf(h1, 0.f);
                orow[q] = r;
            }
        }
        if (v1) {
            float4* orow = reinterpret_cast<float4*>(out + row1 * DIM + o0);
#pragma unroll
            for (int q = 0; q < 4; q++) {
                float l0, h0, l1, h1;
                unpack2(acc1[2 * q + 0], l0, h0);
                unpack2(acc1[2 * q + 1], l1, h1);
                float4 r;
                r.x = fmaxf(l0, 0.f);
                r.y = fmaxf(h0, 0.f);
                r.z = fmaxf(l1, 0.f);
                r.w = fmaxf(h1, 0.f);
                orow[q] = r;
            }
        }
    }
}

// ---------------------------------------------------------------------------
// Launch. Inputs per metadata order:
//   d_in[0] x, d_in[1] edge_index, d_in[2] W_self, d_in[3] b_self,
//   d_in[4] W_neigh, d_in[5] b_neigh
// ---------------------------------------------------------------------------
extern "C" void kernel_launch(void* const* d_in, const int* in_sizes, int n_in,
                              void* d_out, int out_size) {
    const float* x = (const float*)d_in[0];
    const void* edges = d_in[1];
    const float* Ws = (const float*)d_in[2];
    const float* bs = (const float*)d_in[3];
    const float* Wn = (const float*)d_in[4];
    const float* bn = (const float*)d_in[5];
    float* out = (float*)d_out;

    int nwords = in_sizes[1];
    int max_edges = nwords / 2;

    // 0) detect edge dtype
    detect_dtype_kernel<<<1, 256>>>((const int*)edges, nwords);

    // 1) zero agg
    zero_agg_kernel<<<2048, 256>>>();

    // 2) batch-phased scatter: 16 threads/edge, grid.y = batch
    {
        size_t threads_needed = (size_t)max_edges * 16;
        int blocks_x = (int)((threads_needed + 255) / 256);
        dim3 grid(blocks_x, BATCH, 1);
        scatter_kernel<<<grid, 256>>>(x, edges, nwords);
    }

    // 3) fused dual-GEMM (f32x2) + bias + relu: 256 rows per block
    int gblocks = (int)((TOTAL_ROWS + 255) / 256);
    gemm_relu_kernel<<<gblocks, 128>>>(x, Ws, bs, Wn, bn, out);
}